// round 2
// baseline (speedup 1.0000x reference)
#include <cuda_runtime.h>
#include <math.h>

// ---------------------------------------------------------------------------
// Problem constants (fixed shapes for SVTRBlock_43087111914328)
// ---------------------------------------------------------------------------
#define B_    8
#define SEQ   1024
#define DIM   768
#define NHEAD 12
#define HD    64
#define TD    2304          // 3*DIM
#define HMLP  3072          // 4*DIM
#define ROWS  (B_*SEQ)      // 8192

// ---------------------------------------------------------------------------
// Scratch (device globals; no allocation allowed in kernel_launch)
// ---------------------------------------------------------------------------
__device__ float g_qkv[B_ * SEQ * TD];                       //  75.5 MB
__device__ float g_sc[(size_t)B_ * NHEAD * SEQ * SEQ];       // 402.7 MB
__device__ float g_attn[ROWS * DIM];                         //  25.2 MB
__device__ float g_x1[ROWS * DIM];                           //  25.2 MB
__device__ float g_y[ROWS * DIM];                            //  25.2 MB
__device__ float g_h[ROWS * HMLP];                           // 100.7 MB

// ---------------------------------------------------------------------------
// Templated tiled SGEMM with fused epilogues.
//   C[M x N] = op(A) * op(B)
//   A: M x K row-major (lda). BT=false: B is K x N row-major (ldb).
//   BT=true: B is N x K row-major (ldb) -> computes A * B^T (used for Q*K^T).
// Batched via blockIdx.z decomposed as (zb, zh), zh = z % nh.
// All global loads are float4 (strides/offsets are multiples of 4 by shape).
// ---------------------------------------------------------------------------
enum { EPI_NONE = 0, EPI_BIAS = 1, EPI_BIAS_GELU = 2, EPI_BIAS_RES = 3, EPI_SCALE = 4 };

template <int BM, int BN, int BK, int TM, int TN, bool BT, int EPI>
__global__ void __launch_bounds__((BM / TM) * (BN / TN))
gemm_k(const float* __restrict__ A, int lda, long sAb, long sAh,
       const float* __restrict__ Bp, int ldb, long sBb, long sBh,
       float* __restrict__ C, int ldc, long sCb, long sCh,
       const float* __restrict__ bias,
       const float* __restrict__ res, int ldres,
       int K, int nh, float scale)
{
    constexpr int NT = (BM / TM) * (BN / TN);
    const int tid = threadIdx.x;
    const int z  = blockIdx.z;
    const int zb = z / nh;
    const int zh = z - zb * nh;
    A  += (size_t)zb * sAb + (size_t)zh * sAh;
    Bp += (size_t)zb * sBb + (size_t)zh * sBh;
    C  += (size_t)zb * sCb + (size_t)zh * sCh;

    const int rowBase = blockIdx.y * BM;
    const int colBase = blockIdx.x * BN;

    __shared__ float As[BK][BM + 4];
    __shared__ float Bs[BK][BN + 4];

    const int tx = tid % (BN / TN);
    const int ty = tid / (BN / TN);

    float acc[TM][TN];
#pragma unroll
    for (int i = 0; i < TM; i++)
#pragma unroll
        for (int j = 0; j < TN; j++) acc[i][j] = 0.0f;

    for (int k0 = 0; k0 < K; k0 += BK) {
        // ---- A tile (BM x BK), float4 along K, transposed into As[k][m]
        {
            constexpr int V = BM * (BK / 4);         // float4 loads in tile
            for (int i = tid; i < V; i += NT) {
                int m = i / (BK / 4), c = i % (BK / 4);
                float4 v = *(const float4*)&A[(size_t)(rowBase + m) * lda + k0 + 4 * c];
                As[4 * c + 0][m] = v.x;
                As[4 * c + 1][m] = v.y;
                As[4 * c + 2][m] = v.z;
                As[4 * c + 3][m] = v.w;
            }
        }
        // ---- B tile
        if (BT) {
            constexpr int V = BN * (BK / 4);
            for (int i = tid; i < V; i += NT) {
                int j = i / (BK / 4), c = i % (BK / 4);
                float4 v = *(const float4*)&Bp[(size_t)(colBase + j) * ldb + k0 + 4 * c];
                Bs[4 * c + 0][j] = v.x;
                Bs[4 * c + 1][j] = v.y;
                Bs[4 * c + 2][j] = v.z;
                Bs[4 * c + 3][j] = v.w;
            }
        } else {
            constexpr int V = BK * (BN / 4);
            for (int i = tid; i < V; i += NT) {
                int kk = i / (BN / 4), c = i % (BN / 4);
                float4 v = *(const float4*)&Bp[(size_t)(k0 + kk) * ldb + colBase + 4 * c];
                *(float4*)&Bs[kk][4 * c] = v;    // (BN+4)-pad keeps 16B alignment
            }
        }
        __syncthreads();

#pragma unroll
        for (int kk = 0; kk < BK; kk++) {
            float a[TM], b[TN];
#pragma unroll
            for (int i = 0; i < TM; i += 4)
                *(float4*)&a[i] = *(const float4*)&As[kk][ty * TM + i];
#pragma unroll
            for (int j = 0; j < TN; j += 4)
                *(float4*)&b[j] = *(const float4*)&Bs[kk][tx * TN + j];
#pragma unroll
            for (int i = 0; i < TM; i++)
#pragma unroll
                for (int j = 0; j < TN; j++)
                    acc[i][j] = fmaf(a[i], b[j], acc[i][j]);
        }
        __syncthreads();
    }

    // ---- epilogue
#pragma unroll
    for (int i = 0; i < TM; i++) {
        const int r = rowBase + ty * TM + i;
#pragma unroll
        for (int j = 0; j < TN; j++) {
            const int c = colBase + tx * TN + j;
            float v = acc[i][j];
            if (EPI == EPI_SCALE) v *= scale;
            if (EPI == EPI_BIAS || EPI == EPI_BIAS_GELU || EPI == EPI_BIAS_RES)
                v += bias[c];
            if (EPI == EPI_BIAS_GELU)
                v = 0.5f * v * (1.0f + erff(v * 0.70710678118654752f));
            if (EPI == EPI_BIAS_RES)
                v += res[(size_t)r * ldres + c];
            C[(size_t)r * ldc + c] = v;
        }
    }
}

// ---------------------------------------------------------------------------
// Row softmax over 1024 columns (one block = one row, 256 threads, float4)
// ---------------------------------------------------------------------------
__global__ void softmax_1024(float* __restrict__ S)
{
    __shared__ float sm[33];
    const size_t row = blockIdx.x;
    float4* p = reinterpret_cast<float4*>(S + row * 1024);
    float4 v = p[threadIdx.x];

    float m = fmaxf(fmaxf(v.x, v.y), fmaxf(v.z, v.w));
#pragma unroll
    for (int o = 16; o; o >>= 1) m = fmaxf(m, __shfl_xor_sync(0xffffffffu, m, o));
    const int w = threadIdx.x >> 5, l = threadIdx.x & 31;
    if (l == 0) sm[w] = m;
    __syncthreads();
    if (threadIdx.x == 0) {
        float r = sm[0];
#pragma unroll
        for (int i = 1; i < 8; i++) r = fmaxf(r, sm[i]);
        sm[32] = r;
    }
    __syncthreads();
    m = sm[32];

    v.x = __expf(v.x - m); v.y = __expf(v.y - m);
    v.z = __expf(v.z - m); v.w = __expf(v.w - m);
    float s = v.x + v.y + v.z + v.w;
#pragma unroll
    for (int o = 16; o; o >>= 1) s += __shfl_xor_sync(0xffffffffu, s, o);
    __syncthreads();
    if (l == 0) sm[w] = s;
    __syncthreads();
    if (threadIdx.x == 0) {
        float r = 0.0f;
#pragma unroll
        for (int i = 0; i < 8; i++) r += sm[i];
        sm[32] = r;
    }
    __syncthreads();
    const float inv = 1.0f / sm[32];
    v.x *= inv; v.y *= inv; v.z *= inv; v.w *= inv;
    p[threadIdx.x] = v;
}

// ---------------------------------------------------------------------------
// LayerNorm over 768 columns (one block = one row, 256 threads x 3 elems)
// ---------------------------------------------------------------------------
__global__ void layernorm_768(const float* __restrict__ in, float* __restrict__ out,
                              const float* __restrict__ g, const float* __restrict__ bb)
{
    __shared__ float sm[33];
    const size_t row = blockIdx.x;
    const float* p = in + row * DIM;
    const int t = threadIdx.x;
    const float x0 = p[t], x1 = p[t + 256], x2 = p[t + 512];

    float s = x0 + x1 + x2;
#pragma unroll
    for (int o = 16; o; o >>= 1) s += __shfl_xor_sync(0xffffffffu, s, o);
    const int w = t >> 5, l = t & 31;
    if (l == 0) sm[w] = s;
    __syncthreads();
    if (t == 0) {
        float r = 0.0f;
#pragma unroll
        for (int i = 0; i < 8; i++) r += sm[i];
        sm[32] = r;
    }
    __syncthreads();
    const float mu = sm[32] * (1.0f / DIM);

    const float d0 = x0 - mu, d1 = x1 - mu, d2 = x2 - mu;
    float q = d0 * d0 + d1 * d1 + d2 * d2;
#pragma unroll
    for (int o = 16; o; o >>= 1) q += __shfl_xor_sync(0xffffffffu, q, o);
    __syncthreads();
    if (l == 0) sm[w] = q;
    __syncthreads();
    if (t == 0) {
        float r = 0.0f;
#pragma unroll
        for (int i = 0; i < 8; i++) r += sm[i];
        sm[32] = r;
    }
    __syncthreads();
    const float var = sm[32] * (1.0f / DIM);
    const float inv = rsqrtf(var + 1e-6f);

    float* o = out + row * DIM;
    o[t]       = d0 * inv * g[t]       + bb[t];
    o[t + 256] = d1 * inv * g[t + 256] + bb[t + 256];
    o[t + 512] = d2 * inv * g[t + 512] + bb[t + 512];
}

// ---------------------------------------------------------------------------
// Launch
// ---------------------------------------------------------------------------
extern "C" void kernel_launch(void* const* d_in, const int* in_sizes, int n_in,
                              void* d_out, int out_size)
{
    const float* x      = (const float*)d_in[0];
    const float* qkv_w  = (const float*)d_in[1];
    const float* qkv_b  = (const float*)d_in[2];
    const float* proj_w = (const float*)d_in[3];
    const float* proj_b = (const float*)d_in[4];
    const float* ln1_g  = (const float*)d_in[5];
    const float* ln1_b  = (const float*)d_in[6];
    const float* ln2_g  = (const float*)d_in[7];
    const float* ln2_b  = (const float*)d_in[8];
    const float* fc1_w  = (const float*)d_in[9];
    const float* fc1_b  = (const float*)d_in[10];
    const float* fc2_w  = (const float*)d_in[11];
    const float* fc2_b  = (const float*)d_in[12];
    float* out = (float*)d_out;

    float *qkv, *sc, *attn, *x1, *y, *h;
    cudaGetSymbolAddress((void**)&qkv,  g_qkv);
    cudaGetSymbolAddress((void**)&sc,   g_sc);
    cudaGetSymbolAddress((void**)&attn, g_attn);
    cudaGetSymbolAddress((void**)&x1,   g_x1);
    cudaGetSymbolAddress((void**)&y,    g_y);
    cudaGetSymbolAddress((void**)&h,    g_h);

    // 1) QKV projection: [8192,768] @ [768,2304] + b -> g_qkv
    gemm_k<128,128,16,8,8,false,EPI_BIAS><<<dim3(TD/128, ROWS/128, 1), 256>>>(
        x, DIM, 0, 0,
        qkv_w, TD, 0, 0,
        qkv, TD, 0, 0,
        qkv_b, nullptr, 0, DIM, 1, 1.0f);

    // 2) Scores: per (b,h)  S = (Q @ K^T) * hd^-0.5    (both K-major, NT)
    gemm_k<128,128,16,8,8,true,EPI_SCALE><<<dim3(SEQ/128, SEQ/128, B_*NHEAD), 256>>>(
        qkv,        TD, (long)SEQ*TD, HD,            // Q (offset 0)
        qkv + DIM,  TD, (long)SEQ*TD, HD,            // K (offset D)
        sc, SEQ, (long)NHEAD*SEQ*SEQ, (long)SEQ*SEQ,
        nullptr, nullptr, 0, HD, NHEAD, 0.125f);

    // 3) softmax over keys
    softmax_1024<<<B_*NHEAD*SEQ, 256>>>(sc);

    // 4) PV: per (b,h)  O = P @ V  -> written head-interleaved into g_attn [B,N,D]
    gemm_k<128,64,16,8,4,false,EPI_NONE><<<dim3(1, SEQ/128, B_*NHEAD), 256>>>(
        sc, SEQ, (long)NHEAD*SEQ*SEQ, (long)SEQ*SEQ,
        qkv + 2*DIM, TD, (long)SEQ*TD, HD,           // V (offset 2D)
        attn, DIM, (long)SEQ*DIM, HD,
        nullptr, nullptr, 0, SEQ, NHEAD, 1.0f);

    // 5) Proj + bias + residual(x) -> g_y
    gemm_k<128,128,16,8,8,false,EPI_BIAS_RES><<<dim3(DIM/128, ROWS/128, 1), 256>>>(
        attn, DIM, 0, 0,
        proj_w, DIM, 0, 0,
        y, DIM, 0, 0,
        proj_b, x, DIM, DIM, 1, 1.0f);

    // 6) LN1 -> g_x1
    layernorm_768<<<ROWS, 256>>>(y, x1, ln1_g, ln1_b);

    // 7) FC1 + bias + exact GELU -> g_h
    gemm_k<128,128,16,8,8,false,EPI_BIAS_GELU><<<dim3(HMLP/128, ROWS/128, 1), 256>>>(
        x1, DIM, 0, 0,
        fc1_w, HMLP, 0, 0,
        h, HMLP, 0, 0,
        fc1_b, nullptr, 0, DIM, 1, 1.0f);

    // 8) FC2 + bias + residual(x1) -> g_y
    gemm_k<128,128,16,8,8,false,EPI_BIAS_RES><<<dim3(DIM/128, ROWS/128, 1), 256>>>(
        h, HMLP, 0, 0,
        fc2_w, DIM, 0, 0,
        y, DIM, 0, 0,
        fc2_b, x1, DIM, HMLP, 1, 1.0f);

    // 9) LN2 -> out
    layernorm_768<<<ROWS, 256>>>(y, out, ln2_g, ln2_b);
}